// round 1
// baseline (speedup 1.0000x reference)
#include <cuda_runtime.h>
#include <math.h>
#include <stddef.h>

// Problem constants
#define BATCH 32
#define RES   64
#define CDIM  96
#define NHEAD 3
#define HEADD 32
#define GWIN  8
#define LTOT  (RES*RES)          // 4096
#define MTOT  (BATCH*LTOT)       // 131072
#define NWIN  (BATCH*64)         // 2048
#define HID   384
#define SCALEF 0.17677669529663687f  // 32^-0.5

// Scratch buffers (static device globals; no allocation in kernel_launch)
__device__ float g_h  [(size_t)MTOT*CDIM];
__device__ float g_qkv[(size_t)MTOT*3*CDIM];
__device__ float g_o  [(size_t)MTOT*CDIM];
__device__ float g_x1 [(size_t)MTOT*CDIM];
__device__ float g_h2 [(size_t)MTOT*CDIM];
__device__ float g_hid[(size_t)MTOT*HID];
__device__ float g_attn_scr[(size_t)NWIN*NHEAD*64*64];

// ---------------------------------------------------------------------------
// LayerNorm (one warp per token). WIN=true also remaps token order ->
// window-partition order so downstream GEMMs see contiguous window rows.
// ---------------------------------------------------------------------------
template<bool WIN>
__global__ __launch_bounds__(128) void ln_kernel(
    const float* __restrict__ x, const float* __restrict__ g,
    const float* __restrict__ bt, float* __restrict__ outp)
{
    int lane = threadIdx.x & 31;
    int tk = blockIdx.x * 4 + (threadIdx.x >> 5);   // token index 0..MTOT-1
    const float* xr = x + (size_t)tk * CDIM;
    float v0 = xr[lane], v1 = xr[lane+32], v2 = xr[lane+64];
    float s = v0 + v1 + v2;
    #pragma unroll
    for (int o = 16; o; o >>= 1) s += __shfl_xor_sync(0xffffffffu, s, o);
    float mean = s * (1.0f/96.0f);
    float d0 = v0-mean, d1 = v1-mean, d2 = v2-mean;
    float ss = d0*d0 + d1*d1 + d2*d2;
    #pragma unroll
    for (int o = 16; o; o >>= 1) ss += __shfl_xor_sync(0xffffffffu, ss, o);
    float inv = rsqrtf(ss * (1.0f/96.0f) + 1e-5f);

    size_t dst;
    if (WIN) {
        int bb = tk >> 12;          // batch
        int l  = tk & 4095;
        int row = l >> 6, col = l & 63;
        int win = (bb << 6) + ((row >> 3) << 3) + (col >> 3);
        int tt  = ((row & 7) << 3) + (col & 7);
        dst = ((size_t)win * 64 + tt) * CDIM;
    } else {
        dst = (size_t)tk * CDIM;
    }
    float* orow = outp + dst;
    orow[lane]    = d0 * inv * g[lane]    + bt[lane];
    orow[lane+32] = d1 * inv * g[lane+32] + bt[lane+32];
    orow[lane+64] = d2 * inv * g[lane+64] + bt[lane+64];
}

// ---------------------------------------------------------------------------
// Tiled fp32 GEMM: C = A(MxK) * W(KxN) + bias, with fused epilogues.
// BM=128, BN=32, BK=32, 256 threads, 4x4 register tile per thread.
// All dims used here are exact multiples of the tile dims -> no bounds checks.
// EPI: 0 = bias store; 1 = bias+exact GELU; 2 = bias + window-reverse remap +
//      residual(token order) -> out; 3 = bias + residual(same order) -> out.
// ---------------------------------------------------------------------------
template<int EPI>
__global__ __launch_bounds__(256) void gemm_kernel(
    const float* __restrict__ A, const float* __restrict__ W,
    const float* __restrict__ bias, const float* __restrict__ res,
    float* __restrict__ out, int M, int N, int K)
{
    __shared__ float As[32][128];
    __shared__ float Bs[32][32];

    int tid = threadIdx.x;
    int tx = tid & 7;       // 0..7   (column group of 4)
    int ty = tid >> 3;      // 0..31  (row group of 4)
    int m0 = blockIdx.y * 128;
    int n0 = blockIdx.x * 32;

    float acc[4][4] = {};

    int arow = tid >> 3;    // 0..31 base row for A loads
    int ak4  = tid & 7;     // float4 index along K

    for (int k0 = 0; k0 < K; k0 += 32) {
        #pragma unroll
        for (int r = 0; r < 4; r++) {
            int m = arow + r * 32;
            float4 a4 = *(const float4*)(A + (size_t)(m0 + m) * K + k0 + ak4 * 4);
            As[ak4*4+0][m] = a4.x; As[ak4*4+1][m] = a4.y;
            As[ak4*4+2][m] = a4.z; As[ak4*4+3][m] = a4.w;
        }
        {
            int kk = tid >> 3;
            float4 b4 = *(const float4*)(W + (size_t)(k0 + kk) * N + n0 + (tid & 7) * 4);
            *(float4*)&Bs[kk][(tid & 7) * 4] = b4;
        }
        __syncthreads();

        #pragma unroll
        for (int kk = 0; kk < 32; kk++) {
            float4 a = *(const float4*)&As[kk][ty * 4];
            float4 b = *(const float4*)&Bs[kk][tx * 4];
            acc[0][0] += a.x*b.x; acc[0][1] += a.x*b.y; acc[0][2] += a.x*b.z; acc[0][3] += a.x*b.w;
            acc[1][0] += a.y*b.x; acc[1][1] += a.y*b.y; acc[1][2] += a.y*b.z; acc[1][3] += a.y*b.w;
            acc[2][0] += a.z*b.x; acc[2][1] += a.z*b.y; acc[2][2] += a.z*b.z; acc[2][3] += a.z*b.w;
            acc[3][0] += a.w*b.x; acc[3][1] += a.w*b.y; acc[3][2] += a.w*b.z; acc[3][3] += a.w*b.w;
        }
        __syncthreads();
    }

    float bv0 = bias[n0 + tx*4 + 0];
    float bv1 = bias[n0 + tx*4 + 1];
    float bv2 = bias[n0 + tx*4 + 2];
    float bv3 = bias[n0 + tx*4 + 3];

    #pragma unroll
    for (int i = 0; i < 4; i++) {
        int m = m0 + ty * 4 + i;
        float4 v;
        v.x = acc[i][0] + bv0; v.y = acc[i][1] + bv1;
        v.z = acc[i][2] + bv2; v.w = acc[i][3] + bv3;
        if (EPI == 0) {
            *(float4*)(out + (size_t)m * N + n0 + tx * 4) = v;
        } else if (EPI == 1) {
            v.x = v.x * normcdff(v.x);
            v.y = v.y * normcdff(v.y);
            v.z = v.z * normcdff(v.z);
            v.w = v.w * normcdff(v.w);
            *(float4*)(out + (size_t)m * N + n0 + tx * 4) = v;
        } else if (EPI == 2) {
            // m = win*64 + t  ->  token order (b, l); add shortcut x, write x1
            int win = m >> 6, t = m & 63;
            int bb = win >> 6, wi = win & 63;
            int wh = wi >> 3, ww = wi & 7;
            int gh = t >> 3,  gw = t & 7;
            int l = ((wh * 8 + gh) << 6) + ww * 8 + gw;
            size_t off = ((size_t)bb * LTOT + l) * CDIM + n0 + tx * 4;
            float4 r4 = *(const float4*)(res + off);
            v.x += r4.x; v.y += r4.y; v.z += r4.z; v.w += r4.w;
            *(float4*)(out + off) = v;
        } else {  // EPI == 3
            size_t off = (size_t)m * N + n0 + tx * 4;
            float4 r4 = *(const float4*)(res + off);
            v.x += r4.x; v.y += r4.y; v.z += r4.z; v.w += r4.w;
            *(float4*)(out + off) = v;
        }
    }
}

// ---------------------------------------------------------------------------
// Windowed attention + LePE per (window, head). 64 threads = 1 token row each.
// q, probabilities, o-accumulator in registers; K/V in smem (broadcast reads).
// ---------------------------------------------------------------------------
__global__ __launch_bounds__(64) void attn_kernel(
    const float* __restrict__ qkv, const float* __restrict__ wle,
    const float* __restrict__ ble, float* __restrict__ attn_out,
    float* __restrict__ ob)
{
    const int win  = blockIdx.x / NHEAD;
    const int head = blockIdx.x % NHEAD;
    const int t    = threadIdx.x;

    __shared__ float ks[64][36];   // stride 36 floats: 16B aligned rows
    __shared__ float vs[64][36];

    const float* base = qkv + ((size_t)(win * 64 + t)) * (3 * CDIM) + head * HEADD;
    float q[32];
    #pragma unroll
    for (int i = 0; i < 8; i++) {
        float4 fq = *(const float4*)(base + i * 4);
        q[i*4] = fq.x; q[i*4+1] = fq.y; q[i*4+2] = fq.z; q[i*4+3] = fq.w;
        *(float4*)&ks[t][i*4] = *(const float4*)(base + CDIM   + i * 4);
        *(float4*)&vs[t][i*4] = *(const float4*)(base + 2*CDIM + i * 4);
    }
    __syncthreads();

    // scores, 4-wide over j for ILP
    float p[64];
    #pragma unroll
    for (int j0 = 0; j0 < 64; j0 += 4) {
        float a0 = 0.f, a1 = 0.f, a2 = 0.f, a3 = 0.f;
        #pragma unroll
        for (int d4 = 0; d4 < 8; d4++) {
            float4 k0 = *(const float4*)&ks[j0+0][d4*4];
            float4 k1 = *(const float4*)&ks[j0+1][d4*4];
            float4 k2 = *(const float4*)&ks[j0+2][d4*4];
            float4 k3 = *(const float4*)&ks[j0+3][d4*4];
            float q0 = q[d4*4], q1 = q[d4*4+1], q2 = q[d4*4+2], q3 = q[d4*4+3];
            a0 += q0*k0.x + q1*k0.y + q2*k0.z + q3*k0.w;
            a1 += q0*k1.x + q1*k1.y + q2*k1.z + q3*k1.w;
            a2 += q0*k2.x + q1*k2.y + q2*k2.z + q3*k2.w;
            a3 += q0*k3.x + q1*k3.y + q2*k3.z + q3*k3.w;
        }
        p[j0] = a0 * SCALEF; p[j0+1] = a1 * SCALEF;
        p[j0+2] = a2 * SCALEF; p[j0+3] = a3 * SCALEF;
    }

    // softmax over the row
    float mx = -1e30f;
    #pragma unroll
    for (int j = 0; j < 64; j++) mx = fmaxf(mx, p[j]);
    float sum = 0.f;
    #pragma unroll
    for (int j = 0; j < 64; j++) { p[j] = __expf(p[j] - mx); sum += p[j]; }
    float invs = 1.0f / sum;
    #pragma unroll
    for (int j = 0; j < 64; j++) p[j] *= invs;

    // write attention probabilities (part of the output tuple)
    float* ar = attn_out + ((size_t)(win * NHEAD + head) * 64 + t) * 64;
    #pragma unroll
    for (int j4 = 0; j4 < 16; j4++) {
        float4 w; w.x = p[j4*4]; w.y = p[j4*4+1]; w.z = p[j4*4+2]; w.w = p[j4*4+3];
        *(float4*)(ar + j4 * 4) = w;
    }

    // o = p @ V
    float acc[32] = {};
    #pragma unroll
    for (int j = 0; j < 64; j++) {
        float pj = p[j];
        #pragma unroll
        for (int d4 = 0; d4 < 8; d4++) {
            float4 vv = *(const float4*)&vs[j][d4*4];
            acc[d4*4+0] += pj * vv.x; acc[d4*4+1] += pj * vv.y;
            acc[d4*4+2] += pj * vv.z; acc[d4*4+3] += pj * vv.w;
        }
    }

    // LePE: depthwise 3x3 SAME conv on V viewed as (C, 8, 8); spatial = token
    int gh = t >> 3, gw = t & 7;
    #pragma unroll
    for (int d = 0; d < 32; d++) {
        int c = head * HEADD + d;
        float le = 0.f;
        #pragma unroll
        for (int dh = -1; dh <= 1; dh++) {
            int ih = gh + dh;
            if (ih < 0 || ih > 7) continue;
            #pragma unroll
            for (int dw = -1; dw <= 1; dw++) {
                int iw = gw + dw;
                if (iw < 0 || iw > 7) continue;
                le += vs[ih * 8 + iw][d] * __ldg(wle + (size_t)c * 9 + (dh+1)*3 + (dw+1));
            }
        }
        acc[d] += le + __ldg(ble + c);
    }

    float* orow = ob + ((size_t)(win * 64 + t)) * CDIM + head * HEADD;
    #pragma unroll
    for (int d4 = 0; d4 < 8; d4++) {
        float4 w; w.x = acc[d4*4]; w.y = acc[d4*4+1]; w.z = acc[d4*4+2]; w.w = acc[d4*4+3];
        *(float4*)(orow + d4 * 4) = w;
    }
}

// ---------------------------------------------------------------------------
extern "C" void kernel_launch(void* const* d_in, const int* in_sizes, int n_in,
                              void* d_out, int out_size)
{
    const float* x      = (const float*)d_in[0];
    const float* w_qkv  = (const float*)d_in[1];
    const float* b_qkv  = (const float*)d_in[2];
    const float* w_lepe = (const float*)d_in[3];
    const float* b_lepe = (const float*)d_in[4];
    const float* w_proj = (const float*)d_in[5];
    const float* b_proj = (const float*)d_in[6];
    const float* g1     = (const float*)d_in[7];
    const float* bt1    = (const float*)d_in[8];
    const float* g2     = (const float*)d_in[9];
    const float* bt2    = (const float*)d_in[10];
    const float* w_fc1  = (const float*)d_in[11];
    const float* b_fc1  = (const float*)d_in[12];
    const float* w_fc2  = (const float*)d_in[13];
    const float* b_fc2  = (const float*)d_in[14];

    float *h, *qkv, *ob, *x1, *h2, *hid, *ascr;
    cudaGetSymbolAddress((void**)&h,    g_h);
    cudaGetSymbolAddress((void**)&qkv,  g_qkv);
    cudaGetSymbolAddress((void**)&ob,   g_o);
    cudaGetSymbolAddress((void**)&x1,   g_x1);
    cudaGetSymbolAddress((void**)&h2,   g_h2);
    cudaGetSymbolAddress((void**)&hid,  g_hid);
    cudaGetSymbolAddress((void**)&ascr, g_attn_scr);

    const long YE = (long)MTOT * CDIM;                  // 12,582,912
    const long AE = (long)NWIN * NHEAD * 64 * 64;       // 25,165,824
    float* out = (float*)d_out;
    float* y_out = out;
    float* a_out;
    if ((long)out_size >= YE + AE)      { a_out = out + YE; }
    else if ((long)out_size == AE)      { y_out = h; a_out = out; }   // attn-only output
    else                                { a_out = ascr; }             // y-only output

    // 1. LN1 + window partition
    ln_kernel<true><<<MTOT/4, 128>>>(x, g1, bt1, h);
    // 2. qkv GEMM
    gemm_kernel<0><<<dim3(3*CDIM/32, MTOT/128), 256>>>(h, w_qkv, b_qkv, nullptr, qkv, MTOT, 3*CDIM, CDIM);
    // 3. attention + LePE (also writes attn output)
    attn_kernel<<<NWIN*NHEAD, 64>>>(qkv, w_lepe, b_lepe, a_out, ob);
    // 4. proj GEMM + window reverse + shortcut -> x1
    gemm_kernel<2><<<dim3(CDIM/32, MTOT/128), 256>>>(ob, w_proj, b_proj, x, x1, MTOT, CDIM, CDIM);
    // 5. LN2
    ln_kernel<false><<<MTOT/4, 128>>>(x1, g2, bt2, h2);
    // 6. fc1 + GELU
    gemm_kernel<1><<<dim3(HID/32, MTOT/128), 256>>>(h2, w_fc1, b_fc1, nullptr, hid, MTOT, HID, CDIM);
    // 7. fc2 + residual -> y
    gemm_kernel<3><<<dim3(CDIM/32, MTOT/128), 256>>>(hid, w_fc2, b_fc2, x1, y_out, MTOT, CDIM, HID);
}

// round 4
// speedup vs baseline: 2.5710x; 2.5710x over previous
#include <cuda_runtime.h>
#include <cuda_bf16.h>
#include <math.h>
#include <stdint.h>
#include <stddef.h>

// ---------------------------------------------------------------------------
// Problem constants
// ---------------------------------------------------------------------------
#define BATCH 32
#define RES   64
#define CDIM  96
#define NHEAD 3
#define HEADD 32
#define LTOT  (RES*RES)          // 4096
#define MTOT  (BATCH*LTOT)       // 131072
#define NWIN  (BATCH*64)         // 2048
#define HID   384
#define SCALEF 0.17677669529663687f  // 32^-0.5

typedef __nv_bfloat16 bf16;
typedef __nv_bfloat162 bf162;

// Scratch (static device globals; no allocation anywhere)
__device__ __align__(256) bf16  g_h   [(size_t)MTOT*CDIM];
__device__ __align__(256) bf16  g_qkv [(size_t)MTOT*3*CDIM];
__device__ __align__(256) bf16  g_o   [(size_t)MTOT*CDIM];
__device__ __align__(256) float g_x1  [(size_t)MTOT*CDIM];
__device__ __align__(256) bf16  g_h2  [(size_t)MTOT*CDIM];
__device__ __align__(256) bf16  g_hid [(size_t)MTOT*HID];
__device__ __align__(256) float g_scr [(size_t)NWIN*NHEAD*64*64];
__device__ __align__(256) bf16  g_wqkvT[3*CDIM*CDIM];
__device__ __align__(256) bf16  g_wprojT[CDIM*CDIM];
__device__ __align__(256) bf16  g_wfc1T[HID*CDIM];
__device__ __align__(256) bf16  g_wfc2T[CDIM*HID];

// ---------------------------------------------------------------------------
// PTX helpers (sm_80-era; legal on generic sm_103 target)
// ---------------------------------------------------------------------------
__device__ __forceinline__ uint32_t smem_u32(const void* p) {
    uint32_t a;
    asm("{ .reg .u64 t; cvta.to.shared.u64 t, %1; cvt.u32.u64 %0, t; }" : "=r"(a) : "l"(p));
    return a;
}
#define CP_ASYNC16(dst, src) \
    asm volatile("cp.async.cg.shared.global [%0], [%1], 16;" :: "r"(dst), "l"(src))
#define CP_WAIT_ALL() asm volatile("cp.async.wait_all;\n" ::: "memory")

__device__ __forceinline__ void ldm_x4(uint32_t* r, uint32_t addr) {
    asm volatile("ldmatrix.sync.aligned.m8n8.x4.shared.b16 {%0,%1,%2,%3}, [%4];"
        : "=r"(r[0]), "=r"(r[1]), "=r"(r[2]), "=r"(r[3]) : "r"(addr));
}
__device__ __forceinline__ void mma16816(float* d, const uint32_t* a, const uint32_t* b) {
    asm volatile("mma.sync.aligned.m16n8k16.row.col.f32.bf16.bf16.f32 "
        "{%0,%1,%2,%3}, {%4,%5,%6,%7}, {%8,%9}, {%0,%1,%2,%3};"
        : "+f"(d[0]), "+f"(d[1]), "+f"(d[2]), "+f"(d[3])
        : "r"(a[0]), "r"(a[1]), "r"(a[2]), "r"(a[3]), "r"(b[0]), "r"(b[1]));
}

// ---------------------------------------------------------------------------
// Weight transpose + fp32->bf16:  out[n*K+k] = (bf16)W[k*N+n]
// ---------------------------------------------------------------------------
__global__ void wt_kernel(const float* __restrict__ W, bf16* __restrict__ out, int K, int N) {
    int i = blockIdx.x * 256 + threadIdx.x;
    if (i < N * K) {
        int n = i / K, k = i - n * K;
        out[i] = __float2bfloat16(W[(size_t)k * N + n]);
    }
}

// ---------------------------------------------------------------------------
// LayerNorm (one warp/token), bf16 out. WIN=true remaps to window order.
// ---------------------------------------------------------------------------
template<bool WIN>
__global__ __launch_bounds__(128) void ln_kernel(
    const float* __restrict__ x, const float* __restrict__ g,
    const float* __restrict__ bt, bf16* __restrict__ outp)
{
    int lane = threadIdx.x & 31;
    int tk = blockIdx.x * 4 + (threadIdx.x >> 5);
    const float* xr = x + (size_t)tk * CDIM;
    float v0 = xr[lane], v1 = xr[lane+32], v2 = xr[lane+64];
    float s = v0 + v1 + v2;
    #pragma unroll
    for (int o = 16; o; o >>= 1) s += __shfl_xor_sync(0xffffffffu, s, o);
    float mean = s * (1.0f/96.0f);
    float d0 = v0-mean, d1 = v1-mean, d2 = v2-mean;
    float ss = d0*d0 + d1*d1 + d2*d2;
    #pragma unroll
    for (int o = 16; o; o >>= 1) ss += __shfl_xor_sync(0xffffffffu, ss, o);
    float inv = rsqrtf(ss * (1.0f/96.0f) + 1e-5f);

    size_t dst;
    if (WIN) {
        int bb = tk >> 12;
        int l  = tk & 4095;
        int row = l >> 6, col = l & 63;
        int win = (bb << 6) + ((row >> 3) << 3) + (col >> 3);
        int tt  = ((row & 7) << 3) + (col & 7);
        dst = ((size_t)win * 64 + tt) * CDIM;
    } else {
        dst = (size_t)tk * CDIM;
    }
    bf16* orow = outp + dst;
    orow[lane]    = __float2bfloat16(d0 * inv * g[lane]    + bt[lane]);
    orow[lane+32] = __float2bfloat16(d1 * inv * g[lane+32] + bt[lane+32]);
    orow[lane+64] = __float2bfloat16(d2 * inv * g[lane+64] + bt[lane+64]);
}

// ---------------------------------------------------------------------------
// HMMA bf16 GEMM: out(128 x 96 tile) = A(M x K) * Bt(Ntot x K)^T + bias
// BM=128 BN=96 BK=96, 8 warps (4m x 2n), warp tile 32x48, m16n8k16 mma.
// smem rows padded to 104 bf16 (208B) -> ldmatrix conflict-free.
// EPI: 0 = bf16 store (qkv), 1 = exact GELU -> bf16 (fc1),
//      2 = window-reverse + residual -> fp32 (proj), 3 = residual -> fp32 (fc2)
// ---------------------------------------------------------------------------
#define SPAD 104

template<int KTOT, int EPI>
__global__ __launch_bounds__(256) void mm_kernel(
    const bf16* __restrict__ A, const bf16* __restrict__ Bt,
    const float* __restrict__ bias, const float* __restrict__ res,
    void* __restrict__ outp, int Ntot)
{
    __shared__ bf16 As[128][SPAD];
    __shared__ bf16 Bs[96][SPAD];

    int tid = threadIdx.x, lane = tid & 31, wid = tid >> 5;
    int warp_m = wid & 3, warp_n = wid >> 2;     // 4 x 2
    int n0 = blockIdx.x * 96;
    size_t m0 = (size_t)blockIdx.y * 128;

    uint32_t a_base = smem_u32(&As[0][0]);
    uint32_t b_base = smem_u32(&Bs[0][0]);

    float acc[2][6][4] = {};

    int lrow = lane & 15;
    int lcol8 = (lane >> 4) * 8;

    for (int kc = 0; kc < KTOT; kc += 96) {
        // Load A tile: 128 rows x 12 16B-chunks
        {
            const bf16* Ag = A + m0 * KTOT + kc;
            #pragma unroll
            for (int i = 0; i < 6; i++) {
                int idx = tid + i * 256;
                int r = idx / 12, c = idx % 12;
                CP_ASYNC16(a_base + (r * SPAD + c * 8) * 2,
                           Ag + (size_t)r * KTOT + c * 8);
            }
        }
        // Load B tile: 96 rows x 12 chunks
        {
            const bf16* Bg = Bt + (size_t)n0 * KTOT + kc;
            #pragma unroll
            for (int i = 0; i < 5; i++) {
                int idx = tid + i * 256;
                if (idx < 1152) {
                    int r = idx / 12, c = idx % 12;
                    CP_ASYNC16(b_base + (r * SPAD + c * 8) * 2,
                               Bg + (size_t)r * KTOT + c * 8);
                }
            }
        }
        CP_WAIT_ALL();
        __syncthreads();

        #pragma unroll
        for (int ks = 0; ks < 6; ks++) {
            uint32_t a_frag[2][4];
            uint32_t b_frag[6][2];
            #pragma unroll
            for (int mf = 0; mf < 2; mf++) {
                uint32_t addr = a_base +
                    ((warp_m * 32 + mf * 16 + lrow) * SPAD + ks * 16 + lcol8) * 2;
                ldm_x4(a_frag[mf], addr);
            }
            #pragma unroll
            for (int nf2 = 0; nf2 < 3; nf2++) {
                uint32_t r4[4];
                uint32_t addr = b_base +
                    ((warp_n * 48 + nf2 * 16 + lrow) * SPAD + ks * 16 + lcol8) * 2;
                ldm_x4(r4, addr);
                b_frag[nf2*2  ][0] = r4[0]; b_frag[nf2*2  ][1] = r4[2];
                b_frag[nf2*2+1][0] = r4[1]; b_frag[nf2*2+1][1] = r4[3];
            }
            #pragma unroll
            for (int mf = 0; mf < 2; mf++)
                #pragma unroll
                for (int nf = 0; nf < 6; nf++)
                    mma16816(acc[mf][nf], a_frag[mf], b_frag[nf]);
        }
        if (KTOT > 96) __syncthreads();
    }

    // Epilogue
    int wm = warp_m * 32, wn = warp_n * 48;
    int lr = lane >> 2, lc = (lane & 3) * 2;
    #pragma unroll
    for (int mf = 0; mf < 2; mf++) {
        #pragma unroll
        for (int half = 0; half < 2; half++) {
            int m = (int)m0 + wm + mf * 16 + lr + half * 8;
            size_t rowoff;
            if (EPI == 2) {
                int win = m >> 6, t = m & 63;
                int bb = win >> 6, wi = win & 63;
                int wh = wi >> 3, ww = wi & 7;
                int gh = t >> 3,  gw = t & 7;
                int l = ((wh * 8 + gh) << 6) + ww * 8 + gw;
                rowoff = ((size_t)bb * LTOT + l) * CDIM;
            } else {
                rowoff = (size_t)m * Ntot;
            }
            #pragma unroll
            for (int nf = 0; nf < 6; nf++) {
                int col = n0 + wn + nf * 8 + lc;
                float c0 = acc[mf][nf][half * 2 + 0] + __ldg(bias + col);
                float c1 = acc[mf][nf][half * 2 + 1] + __ldg(bias + col + 1);
                if (EPI == 0 || EPI == 1) {
                    if (EPI == 1) { c0 = c0 * normcdff(c0); c1 = c1 * normcdff(c1); }
                    *(bf162*)((bf16*)outp + rowoff + col) =
                        __float22bfloat162_rn(make_float2(c0, c1));
                } else {
                    const float2 rv = *(const float2*)(res + rowoff + col);
                    float2 v; v.x = c0 + rv.x; v.y = c1 + rv.y;
                    *(float2*)((float*)outp + rowoff + col) = v;
                }
            }
        }
    }
}

// ---------------------------------------------------------------------------
// Windowed attention + LePE (bf16 qkv in, fp32 probs out, bf16 o out)
// ---------------------------------------------------------------------------
__global__ __launch_bounds__(64) void attn_kernel(
    const bf16* __restrict__ qkv, const float* __restrict__ wle,
    const float* __restrict__ ble, float* __restrict__ attn_out,
    bf16* __restrict__ ob)
{
    const int win  = blockIdx.x / NHEAD;
    const int head = blockIdx.x % NHEAD;
    const int t    = threadIdx.x;

    __shared__ float ks[64][36];
    __shared__ float vs[64][36];

    const bf16* base = qkv + (size_t)(win * 64 + t) * (3 * CDIM) + head * HEADD;
    float q[32];
    #pragma unroll
    for (int i = 0; i < 4; i++) {
        uint4 rq = *(const uint4*)(base + i * 8);
        uint4 rk = *(const uint4*)(base + CDIM + i * 8);
        uint4 rv = *(const uint4*)(base + 2 * CDIM + i * 8);
        const bf162* pq = (const bf162*)&rq;
        const bf162* pk = (const bf162*)&rk;
        const bf162* pv = (const bf162*)&rv;
        #pragma unroll
        for (int j = 0; j < 4; j++) {
            float2 fq = __bfloat1622float2(pq[j]);
            float2 fk = __bfloat1622float2(pk[j]);
            float2 fv = __bfloat1622float2(pv[j]);
            q[i*8 + 2*j] = fq.x; q[i*8 + 2*j + 1] = fq.y;
            ks[t][i*8 + 2*j] = fk.x; ks[t][i*8 + 2*j + 1] = fk.y;
            vs[t][i*8 + 2*j] = fv.x; vs[t][i*8 + 2*j + 1] = fv.y;
        }
    }
    __syncthreads();

    float p[64];
    #pragma unroll
    for (int j0 = 0; j0 < 64; j0 += 4) {
        float a0 = 0.f, a1 = 0.f, a2 = 0.f, a3 = 0.f;
        #pragma unroll
        for (int d4 = 0; d4 < 8; d4++) {
            float4 k0 = *(const float4*)&ks[j0+0][d4*4];
            float4 k1 = *(const float4*)&ks[j0+1][d4*4];
            float4 k2 = *(const float4*)&ks[j0+2][d4*4];
            float4 k3 = *(const float4*)&ks[j0+3][d4*4];
            float q0 = q[d4*4], q1 = q[d4*4+1], q2 = q[d4*4+2], q3 = q[d4*4+3];
            a0 += q0*k0.x + q1*k0.y + q2*k0.z + q3*k0.w;
            a1 += q0*k1.x + q1*k1.y + q2*k1.z + q3*k1.w;
            a2 += q0*k2.x + q1*k2.y + q2*k2.z + q3*k2.w;
            a3 += q0*k3.x + q1*k3.y + q2*k3.z + q3*k3.w;
        }
        p[j0] = a0 * SCALEF; p[j0+1] = a1 * SCALEF;
        p[j0+2] = a2 * SCALEF; p[j0+3] = a3 * SCALEF;
    }

    float mx = -1e30f;
    #pragma unroll
    for (int j = 0; j < 64; j++) mx = fmaxf(mx, p[j]);
    float sum = 0.f;
    #pragma unroll
    for (int j = 0; j < 64; j++) { p[j] = __expf(p[j] - mx); sum += p[j]; }
    float invs = 1.0f / sum;
    #pragma unroll
    for (int j = 0; j < 64; j++) p[j] *= invs;

    float* ar = attn_out + ((size_t)(win * NHEAD + head) * 64 + t) * 64;
    #pragma unroll
    for (int j4 = 0; j4 < 16; j4++) {
        float4 w; w.x = p[j4*4]; w.y = p[j4*4+1]; w.z = p[j4*4+2]; w.w = p[j4*4+3];
        *(float4*)(ar + j4 * 4) = w;
    }

    float acc[32] = {};
    #pragma unroll
    for (int j = 0; j < 64; j++) {
        float pj = p[j];
        #pragma unroll
        for (int d4 = 0; d4 < 8; d4++) {
            float4 vv = *(const float4*)&vs[j][d4*4];
            acc[d4*4+0] += pj * vv.x; acc[d4*4+1] += pj * vv.y;
            acc[d4*4+2] += pj * vv.z; acc[d4*4+3] += pj * vv.w;
        }
    }

    int gh = t >> 3, gw = t & 7;
    #pragma unroll
    for (int d = 0; d < 32; d++) {
        int c = head * HEADD + d;
        float le = 0.f;
        #pragma unroll
        for (int dh = -1; dh <= 1; dh++) {
            int ih = gh + dh;
            if (ih < 0 || ih > 7) continue;
            #pragma unroll
            for (int dw = -1; dw <= 1; dw++) {
                int iw = gw + dw;
                if (iw < 0 || iw > 7) continue;
                le += vs[ih * 8 + iw][d] * __ldg(wle + (size_t)c * 9 + (dh+1)*3 + (dw+1));
            }
        }
        acc[d] += le + __ldg(ble + c);
    }

    bf162 hh[16];
    #pragma unroll
    for (int j = 0; j < 16; j++)
        hh[j] = __float22bfloat162_rn(make_float2(acc[2*j], acc[2*j+1]));
    uint4* orow = (uint4*)(ob + (size_t)(win * 64 + t) * CDIM + head * HEADD);
    const uint4* src = (const uint4*)hh;
    orow[0] = src[0]; orow[1] = src[1]; orow[2] = src[2]; orow[3] = src[3];
}

// ---------------------------------------------------------------------------
extern "C" void kernel_launch(void* const* d_in, const int* in_sizes, int n_in,
                              void* d_out, int out_size)
{
    const float* x      = (const float*)d_in[0];
    const float* w_qkv  = (const float*)d_in[1];
    const float* b_qkv  = (const float*)d_in[2];
    const float* w_lepe = (const float*)d_in[3];
    const float* b_lepe = (const float*)d_in[4];
    const float* w_proj = (const float*)d_in[5];
    const float* b_proj = (const float*)d_in[6];
    const float* g1     = (const float*)d_in[7];
    const float* bt1    = (const float*)d_in[8];
    const float* g2     = (const float*)d_in[9];
    const float* bt2    = (const float*)d_in[10];
    const float* w_fc1  = (const float*)d_in[11];
    const float* b_fc1  = (const float*)d_in[12];
    const float* w_fc2  = (const float*)d_in[13];
    const float* b_fc2  = (const float*)d_in[14];

    bf16 *h, *qkv, *ob, *h2, *hid, *wq, *wp, *w1, *w2;
    float *x1, *scr;
    cudaGetSymbolAddress((void**)&h,   g_h);
    cudaGetSymbolAddress((void**)&qkv, g_qkv);
    cudaGetSymbolAddress((void**)&ob,  g_o);
    cudaGetSymbolAddress((void**)&x1,  g_x1);
    cudaGetSymbolAddress((void**)&h2,  g_h2);
    cudaGetSymbolAddress((void**)&hid, g_hid);
    cudaGetSymbolAddress((void**)&scr, g_scr);
    cudaGetSymbolAddress((void**)&wq,  g_wqkvT);
    cudaGetSymbolAddress((void**)&wp,  g_wprojT);
    cudaGetSymbolAddress((void**)&w1,  g_wfc1T);
    cudaGetSymbolAddress((void**)&w2,  g_wfc2T);

    const long YE = (long)MTOT * CDIM;                  // 12,582,912
    const long AE = (long)NWIN * NHEAD * 64 * 64;       // 25,165,824
    float* out = (float*)d_out;
    float* y_out = out;
    float* a_out;
    if ((long)out_size >= YE + AE)      { a_out = out + YE; }
    else if ((long)out_size == AE)      { y_out = scr; a_out = out; }
    else                                { a_out = scr; }

    // 0. weight transposes (fp32 -> bf16, [N][K])
    wt_kernel<<<(3*CDIM*CDIM + 255)/256, 256>>>(w_qkv, wq, CDIM, 3*CDIM);
    wt_kernel<<<(CDIM*CDIM   + 255)/256, 256>>>(w_proj, wp, CDIM, CDIM);
    wt_kernel<<<(HID*CDIM    + 255)/256, 256>>>(w_fc1, w1, CDIM, HID);
    wt_kernel<<<(CDIM*HID    + 255)/256, 256>>>(w_fc2, w2, HID, CDIM);
    // 1. LN1 + window partition -> bf16
    ln_kernel<true><<<MTOT/4, 128>>>(x, g1, bt1, h);
    // 2. qkv GEMM -> bf16
    mm_kernel<96,0><<<dim3(3, MTOT/128), 256>>>(h, wq, b_qkv, nullptr, qkv, 3*CDIM);
    // 3. attention + LePE
    attn_kernel<<<NWIN*NHEAD, 64>>>(qkv, w_lepe, b_lepe, a_out, ob);
    // 4. proj GEMM + window reverse + shortcut -> x1 (fp32)
    mm_kernel<96,2><<<dim3(1, MTOT/128), 256>>>(ob, wp, b_proj, x, x1, CDIM);
    // 5. LN2 -> bf16
    ln_kernel<false><<<MTOT/4, 128>>>(x1, g2, bt2, h2);
    // 6. fc1 + exact GELU -> bf16
    mm_kernel<96,1><<<dim3(4, MTOT/128), 256>>>(h2, w1, b_fc1, nullptr, hid, HID);
    // 7. fc2 + residual -> y (fp32)
    mm_kernel<384,3><<<dim3(1, MTOT/128), 256>>>(hid, w2, b_fc2, x1, y_out, CDIM);
}